// round 14
// baseline (speedup 1.0000x reference)
#include <cuda_runtime.h>
#include <cuda_fp16.h>
#include <stdint.h>
#include <math.h>

// Causal MHA forward: fp16 pre-pass for K/V + cp.async-staged fp16 mma kernel.
// BQ=256 (8 warps x 32 rows), BK=64, double buffer, 1 barrier/tile,
// per-warp chunk rotation (stall decorrelation), half2 l-accumulation.
// B=4, L=2048, H=16, E=64. [B,L,H,E] fp32 in/out.

#define HEADS 16
#define SEQ   2048
#define EDIM  64
#define BQ    256
#define BK    64
#define ROWS  1024           // H*E elements between seq positions
#define KROW  144            // smem bytes per key row (64 half + 8 pad)
#define TILEB (BK * KROW)    // 9216 bytes per tile buffer
#define QSC   0.18033688011112042f   // 0.125 * log2(e)
#define NELEM (4 * SEQ * HEADS * EDIM)   // 8388608

__device__ __half2 d_Kh[NELEM / 2];   // fp16 K, same [B,L,H,E] layout
__device__ __half2 d_Vh[NELEM / 2];   // fp16 V

__device__ __forceinline__ uint32_t smem_u32(const void* p) {
    uint32_t a;
    asm("{ .reg .u64 t; cvta.to.shared.u64 t, %1; cvt.u32.u64 %0, t; }"
        : "=r"(a) : "l"(p));
    return a;
}
__device__ __forceinline__ uint32_t f2h2(float a, float b) {
    __half2 h = __floats2half2_rn(a, b);
    return *reinterpret_cast<uint32_t*>(&h);
}
__device__ __forceinline__ uint32_t ex2h2(uint32_t x) {
    uint32_t r;
    asm("ex2.approx.f16x2 %0, %1;" : "=r"(r) : "r"(x));
    return r;
}
__device__ __forceinline__ uint32_t hadd2u(uint32_t a, uint32_t b) {
    __half2 r = __hadd2(*reinterpret_cast<__half2*>(&a),
                        *reinterpret_cast<__half2*>(&b));
    return *reinterpret_cast<uint32_t*>(&r);
}
__device__ __forceinline__ float2 h22f2(uint32_t x) {
    return __half22float2(*reinterpret_cast<__half2*>(&x));
}
__device__ __forceinline__ void cp16(uint32_t dst, const void* src) {
    asm volatile("cp.async.cg.shared.global [%0], [%1], 16;"
                 :: "r"(dst), "l"(src));
}
#define CP_COMMIT() asm volatile("cp.async.commit_group;")
#define CP_WAIT0()  asm volatile("cp.async.wait_group 0;" ::: "memory")

__device__ __forceinline__ void ldsm_x4(uint32_t* r, uint32_t addr) {
    asm volatile("ldmatrix.sync.aligned.m8n8.x4.shared.b16 {%0,%1,%2,%3}, [%4];"
                 : "=r"(r[0]), "=r"(r[1]), "=r"(r[2]), "=r"(r[3]) : "r"(addr));
}
__device__ __forceinline__ void ldsm_x4_t(uint32_t* r, uint32_t addr) {
    asm volatile("ldmatrix.sync.aligned.m8n8.x4.trans.shared.b16 {%0,%1,%2,%3}, [%4];"
                 : "=r"(r[0]), "=r"(r[1]), "=r"(r[2]), "=r"(r[3]) : "r"(addr));
}
__device__ __forceinline__ void mma_f16(float* c, const uint32_t* a,
                                        uint32_t b0, uint32_t b1) {
    asm("mma.sync.aligned.m16n8k16.row.col.f32.f16.f16.f32 "
        "{%0,%1,%2,%3}, {%4,%5,%6,%7}, {%8,%9}, {%0,%1,%2,%3};"
        : "+f"(c[0]), "+f"(c[1]), "+f"(c[2]), "+f"(c[3])
        : "r"(a[0]), "r"(a[1]), "r"(a[2]), "r"(a[3]), "r"(b0), "r"(b1));
}

// ---- pre-pass: fp32 -> fp16 conversion of K and V ----
__global__ __launch_bounds__(256)
void cvt_kernel(const float* __restrict__ K, const float* __restrict__ V) {
    int stride = gridDim.x * blockDim.x;
    for (int i = blockIdx.x * blockDim.x + threadIdx.x;
         i < NELEM / 4; i += stride) {
        float4 k = reinterpret_cast<const float4*>(K)[i];
        float4 v = reinterpret_cast<const float4*>(V)[i];
        uint2 kk, vv;
        kk.x = f2h2(k.x, k.y); kk.y = f2h2(k.z, k.w);
        vv.x = f2h2(v.x, v.y); vv.y = f2h2(v.z, v.w);
        reinterpret_cast<uint2*>(d_Kh)[i] = kk;
        reinterpret_cast<uint2*>(d_Vh)[i] = vv;
    }
}

__global__ __launch_bounds__(256, 2)
void fa_f16_kernel(const float* __restrict__ Q, float* __restrict__ O)
{
    __shared__ uint8_t sK[2][TILEB];
    __shared__ uint8_t sV[2][TILEB];

    const int tid  = threadIdx.x;
    const int w    = tid >> 5;          // 0..7
    const int lane = tid & 31;
    const int g    = lane >> 2;
    const int t4   = lane & 3;
    const int qi   = gridDim.x - 1 - blockIdx.x;     // heavy q-tiles first
    const int bh   = blockIdx.y;
    const int b    = bh / HEADS;
    const int h    = bh % HEADS;
    const size_t base = (((size_t)b * SEQ) * HEADS + h) * EDIM;

    // ---- Q A-fragments: 2 x 16-row m-tiles per warp, fp16, base-2 scaled ----
    uint32_t qa[2][4][4];
    #pragma unroll
    for (int mi = 0; mi < 2; mi++) {
        const float* Qr0 = Q + base
            + (size_t)(qi * BQ + w * 32 + mi * 16 + g) * ROWS;
        const float* Qr1 = Qr0 + (size_t)8 * ROWS;
        #pragma unroll
        for (int kc = 0; kc < 4; kc++) {
            int e0 = kc * 16 + 2 * t4;
            float2 x0 = *reinterpret_cast<const float2*>(Qr0 + e0);
            float2 x1 = *reinterpret_cast<const float2*>(Qr1 + e0);
            float2 x2 = *reinterpret_cast<const float2*>(Qr0 + e0 + 8);
            float2 x3 = *reinterpret_cast<const float2*>(Qr1 + e0 + 8);
            qa[mi][kc][0] = f2h2(x0.x * QSC, x0.y * QSC);
            qa[mi][kc][1] = f2h2(x1.x * QSC, x1.y * QSC);
            qa[mi][kc][2] = f2h2(x2.x * QSC, x2.y * QSC);
            qa[mi][kc][3] = f2h2(x3.x * QSC, x3.y * QSC);
        }
    }

    // per-lane ldmatrix base offsets (bytes), buffer 0
    const uint32_t ks_base = smem_u32(sK)
        + (uint32_t)((((lane >> 4) & 1) * 8 + (lane & 7)) * KROW)
        + (uint32_t)(((lane >> 3) & 1) * 16);
    const uint32_t vs_base = smem_u32(sV)
        + (uint32_t)((((lane >> 3) & 1) * 8 + (lane & 7)) * KROW)
        + (uint32_t)(((lane >> 4) & 1) * 16);

    float o[2][8][4];
    #pragma unroll
    for (int mi = 0; mi < 2; mi++)
        #pragma unroll
        for (int nt = 0; nt < 8; nt++)
            #pragma unroll
            for (int c = 0; c < 4; c++) o[mi][nt][c] = 0.f;
    float lac[2][2] = {{0.f, 0.f}, {0.f, 0.f}};

    const int ktmax = 4 * qi + 3;
    const int rowg    = qi * BQ + w * 32 + g;    // global row: mi=0, c0/c1
    const int rowlast = qi * BQ + w * 32 + 31;

    // staging coords: thread -> 32 contiguous bytes of one key row
    const int skey = tid >> 2;                    // key row 0..63
    const int sec  = (tid & 3) * 32;              // byte offset within 128B row
    const char* Ksrc0 = reinterpret_cast<const char*>(d_Kh)
        + 2 * (base + (size_t)skey * ROWS) + sec;
    const char* Vsrc0 = reinterpret_cast<const char*>(d_Vh)
        + 2 * (base + (size_t)skey * ROWS) + sec;
    const uint32_t kd0 = smem_u32(sK) + (uint32_t)(skey * KROW + sec);
    const uint32_t vd0 = smem_u32(sV) + (uint32_t)(skey * KROW + sec);

    auto stage = [&](int kt2, int buf) {
        size_t goff = (size_t)kt2 * BK * ROWS * 2;
        uint32_t so  = (uint32_t)(buf * TILEB);
        cp16(kd0 + so,      Ksrc0 + goff);
        cp16(kd0 + so + 16, Ksrc0 + goff + 16);
        cp16(vd0 + so,      Vsrc0 + goff);
        cp16(vd0 + so + 16, Vsrc0 + goff + 16);
    };

    // prologue: tile 0 into buffer 0
    stage(0, 0);
    CP_COMMIT();
    CP_WAIT0();
    __syncthreads();

    for (int kt = 0; kt <= ktmax; kt++) {
        const int cur = kt & 1;

        // stage tile kt+1 into the other buffer (async, fire-and-forget)
        if (kt < ktmax) { stage(kt + 1, cur ^ 1); CP_COMMIT(); }

        if (rowlast >= kt * BK) {          // warp not fully masked
            const uint32_t ksb = ks_base + (uint32_t)(cur * TILEB);
            const uint32_t vsb = vs_base + (uint32_t)(cur * TILEB);
            const bool diag = (kt >= 4 * qi);
            const int  rr0  = rowg - kt * BK;

            // per-warp rotated chunk order: decorrelate SMSP stall points
            #pragma unroll
            for (int jj = 0; jj < 4; jj++) {
                const int j = (jj + w) & 3;
                if (diag && kt * BK + j * 16 > rowlast) continue;  // all-masked

                float s[2][2][4];
                #pragma unroll
                for (int mi = 0; mi < 2; mi++)
                    #pragma unroll
                    for (int hh = 0; hh < 2; hh++)
                        #pragma unroll
                        for (int c = 0; c < 4; c++) s[mi][hh][c] = 0.f;

                #pragma unroll
                for (int kc = 0; kc < 4; kc++) {
                    uint32_t kr[4];
                    ldsm_x4(kr, ksb + (uint32_t)(j * 16 * KROW + kc * 32));
                    mma_f16(s[0][0], qa[0][kc], kr[0], kr[1]);
                    mma_f16(s[0][1], qa[0][kc], kr[2], kr[3]);
                    mma_f16(s[1][0], qa[1][kc], kr[0], kr[1]);
                    mma_f16(s[1][1], qa[1][kc], kr[2], kr[3]);
                }

                uint32_t pa[2][4];
                #pragma unroll
                for (int mi = 0; mi < 2; mi++) {
                    float* sl = s[mi][0];
                    float* sh = s[mi][1];
                    if (diag) {
                        int r0 = rr0 + mi * 16, r1 = r0 + 8;
                        int cl = j * 16 + 2 * t4;
                        int ch = cl + 8;
                        if (cl     > r0) sl[0] = -1e30f;
                        if (cl + 1 > r0) sl[1] = -1e30f;
                        if (cl     > r1) sl[2] = -1e30f;
                        if (cl + 1 > r1) sl[3] = -1e30f;
                        if (ch     > r0) sh[0] = -1e30f;
                        if (ch + 1 > r0) sh[1] = -1e30f;
                        if (ch     > r1) sh[2] = -1e30f;
                        if (ch + 1 > r1) sh[3] = -1e30f;
                    }
                    pa[mi][0] = ex2h2(f2h2(sl[0], sl[1]));   // row g,   keys lo
                    pa[mi][1] = ex2h2(f2h2(sl[2], sl[3]));   // row g+8
                    pa[mi][2] = ex2h2(f2h2(sh[0], sh[1]));   // row g,   keys hi
                    pa[mi][3] = ex2h2(f2h2(sh[2], sh[3]));   // row g+8
                    // half2 fold: row-g pair and row-g+8 pair, then to fp32
                    uint32_t h0 = hadd2u(pa[mi][0], pa[mi][2]);
                    uint32_t h1 = hadd2u(pa[mi][1], pa[mi][3]);
                    float2 f0 = h22f2(h0), f1 = h22f2(h1);
                    lac[mi][0] += f0.x + f0.y;
                    lac[mi][1] += f1.x + f1.y;
                }

                #pragma unroll
                for (int nt = 0; nt < 4; nt++) {
                    uint32_t vr[4];
                    ldsm_x4_t(vr, vsb + (uint32_t)(j * 16 * KROW + nt * 32));
                    mma_f16(o[0][2 * nt],     pa[0], vr[0], vr[1]);
                    mma_f16(o[0][2 * nt + 1], pa[0], vr[2], vr[3]);
                    mma_f16(o[1][2 * nt],     pa[1], vr[0], vr[1]);
                    mma_f16(o[1][2 * nt + 1], pa[1], vr[2], vr[3]);
                }
            }
        }

        CP_WAIT0();        // tile kt+1 landed (full tile of compute since issue)
        __syncthreads();   // visibility + compute-done before next overwrite
    }

    // ---- epilogue: rowsum across quad, normalize, store ----
    #pragma unroll
    for (int mi = 0; mi < 2; mi++) {
        float l0 = lac[mi][0], l1 = lac[mi][1];
        l0 += __shfl_xor_sync(0xffffffffu, l0, 1);
        l0 += __shfl_xor_sync(0xffffffffu, l0, 2);
        l1 += __shfl_xor_sync(0xffffffffu, l1, 1);
        l1 += __shfl_xor_sync(0xffffffffu, l1, 2);
        float inv0 = 1.0f / l0, inv1 = 1.0f / l1;

        float* Or0 = O + base
            + (size_t)(qi * BQ + w * 32 + mi * 16 + g) * ROWS;
        float* Or1 = Or0 + (size_t)8 * ROWS;
        #pragma unroll
        for (int nt = 0; nt < 8; nt++) {
            int col = nt * 8 + 2 * t4;
            *reinterpret_cast<float2*>(Or0 + col) =
                make_float2(o[mi][nt][0] * inv0, o[mi][nt][1] * inv0);
            *reinterpret_cast<float2*>(Or1 + col) =
                make_float2(o[mi][nt][2] * inv1, o[mi][nt][3] * inv1);
        }
    }
}

extern "C" void kernel_launch(void* const* d_in, const int* in_sizes, int n_in,
                              void* d_out, int out_size)
{
    const float* Q = (const float*)d_in[0];
    const float* K = (const float*)d_in[1];
    const float* V = (const float*)d_in[2];
    float* O = (float*)d_out;

    const int Btot = in_sizes[0] / (SEQ * HEADS * EDIM);   // 4

    cvt_kernel<<<1024, 256>>>(K, V);

    dim3 grid(SEQ / BQ, Btot * HEADS);   // (8, 64)
    dim3 block(256);
    fa_f16_kernel<<<grid, block>>>(Q, O);
}

// round 15
// speedup vs baseline: 1.0093x; 1.0093x over previous
#include <cuda_runtime.h>
#include <cuda_fp16.h>
#include <stdint.h>
#include <math.h>

// Causal MHA forward: fp16 pre-pass for K/V + cp.async-staged fp16 mma kernel.
// BQ=256 (8 warps x 32 rows), BK=64, double buffer, 1 barrier/tile,
// per-warp chunk rotation (stall decorrelation), half2 l-accumulation.
// B=4, L=2048, H=16, E=64. [B,L,H,E] fp32 in/out.

#define HEADS 16
#define SEQ   2048
#define EDIM  64
#define BQ    256
#define BK    64
#define ROWS  1024           // H*E elements between seq positions
#define KROW  144            // smem bytes per key row (64 half + 8 pad)
#define TILEB (BK * KROW)    // 9216 bytes per tile buffer
#define QSC   0.18033688011112042f   // 0.125 * log2(e)
#define NELEM (4 * SEQ * HEADS * EDIM)   // 8388608

__device__ __half2 d_Kh[NELEM / 2];   // fp16 K, same [B,L,H,E] layout
__device__ __half2 d_Vh[NELEM / 2];   // fp16 V

__device__ __forceinline__ uint32_t smem_u32(const void* p) {
    uint32_t a;
    asm("{ .reg .u64 t; cvta.to.shared.u64 t, %1; cvt.u32.u64 %0, t; }"
        : "=r"(a) : "l"(p));
    return a;
}
__device__ __forceinline__ uint32_t f2h2(float a, float b) {
    __half2 h = __floats2half2_rn(a, b);
    return *reinterpret_cast<uint32_t*>(&h);
}
__device__ __forceinline__ uint32_t ex2h2(uint32_t x) {
    uint32_t r;
    asm("ex2.approx.f16x2 %0, %1;" : "=r"(r) : "r"(x));
    return r;
}
__device__ __forceinline__ uint32_t hadd2u(uint32_t a, uint32_t b) {
    __half2 r = __hadd2(*reinterpret_cast<__half2*>(&a),
                        *reinterpret_cast<__half2*>(&b));
    return *reinterpret_cast<uint32_t*>(&r);
}
__device__ __forceinline__ float2 h22f2(uint32_t x) {
    return __half22float2(*reinterpret_cast<__half2*>(&x));
}
__device__ __forceinline__ void cp16(uint32_t dst, const void* src) {
    asm volatile("cp.async.cg.shared.global [%0], [%1], 16;"
                 :: "r"(dst), "l"(src));
}
#define CP_COMMIT() asm volatile("cp.async.commit_group;")
#define CP_WAIT0()  asm volatile("cp.async.wait_group 0;" ::: "memory")

__device__ __forceinline__ void ldsm_x4(uint32_t* r, uint32_t addr) {
    asm volatile("ldmatrix.sync.aligned.m8n8.x4.shared.b16 {%0,%1,%2,%3}, [%4];"
                 : "=r"(r[0]), "=r"(r[1]), "=r"(r[2]), "=r"(r[3]) : "r"(addr));
}
__device__ __forceinline__ void ldsm_x4_t(uint32_t* r, uint32_t addr) {
    asm volatile("ldmatrix.sync.aligned.m8n8.x4.trans.shared.b16 {%0,%1,%2,%3}, [%4];"
                 : "=r"(r[0]), "=r"(r[1]), "=r"(r[2]), "=r"(r[3]) : "r"(addr));
}
__device__ __forceinline__ void mma_f16(float* c, const uint32_t* a,
                                        uint32_t b0, uint32_t b1) {
    asm("mma.sync.aligned.m16n8k16.row.col.f32.f16.f16.f32 "
        "{%0,%1,%2,%3}, {%4,%5,%6,%7}, {%8,%9}, {%0,%1,%2,%3};"
        : "+f"(c[0]), "+f"(c[1]), "+f"(c[2]), "+f"(c[3])
        : "r"(a[0]), "r"(a[1]), "r"(a[2]), "r"(a[3]), "r"(b0), "r"(b1));
}

// ---- pre-pass: fp32 -> fp16 conversion of K and V ----
__global__ __launch_bounds__(256)
void cvt_kernel(const float* __restrict__ K, const float* __restrict__ V) {
    int stride = gridDim.x * blockDim.x;
    for (int i = blockIdx.x * blockDim.x + threadIdx.x;
         i < NELEM / 4; i += stride) {
        float4 k = reinterpret_cast<const float4*>(K)[i];
        float4 v = reinterpret_cast<const float4*>(V)[i];
        uint2 kk, vv;
        kk.x = f2h2(k.x, k.y); kk.y = f2h2(k.z, k.w);
        vv.x = f2h2(v.x, v.y); vv.y = f2h2(v.z, v.w);
        reinterpret_cast<uint2*>(d_Kh)[i] = kk;
        reinterpret_cast<uint2*>(d_Vh)[i] = vv;
    }
}

__global__ __launch_bounds__(256, 2)
void fa_f16_kernel(const float* __restrict__ Q, float* __restrict__ O)
{
    __shared__ uint8_t sK[2][TILEB];
    __shared__ uint8_t sV[2][TILEB];

    const int tid  = threadIdx.x;
    const int w    = tid >> 5;          // 0..7
    const int lane = tid & 31;
    const int g    = lane >> 2;
    const int t4   = lane & 3;
    const int qi   = gridDim.x - 1 - blockIdx.x;     // heavy q-tiles first
    const int bh   = blockIdx.y;
    const int b    = bh / HEADS;
    const int h    = bh % HEADS;
    const size_t base = (((size_t)b * SEQ) * HEADS + h) * EDIM;

    // ---- Q A-fragments: 2 x 16-row m-tiles per warp, fp16, base-2 scaled ----
    uint32_t qa[2][4][4];
    #pragma unroll
    for (int mi = 0; mi < 2; mi++) {
        const float* Qr0 = Q + base
            + (size_t)(qi * BQ + w * 32 + mi * 16 + g) * ROWS;
        const float* Qr1 = Qr0 + (size_t)8 * ROWS;
        #pragma unroll
        for (int kc = 0; kc < 4; kc++) {
            int e0 = kc * 16 + 2 * t4;
            float2 x0 = *reinterpret_cast<const float2*>(Qr0 + e0);
            float2 x1 = *reinterpret_cast<const float2*>(Qr1 + e0);
            float2 x2 = *reinterpret_cast<const float2*>(Qr0 + e0 + 8);
            float2 x3 = *reinterpret_cast<const float2*>(Qr1 + e0 + 8);
            qa[mi][kc][0] = f2h2(x0.x * QSC, x0.y * QSC);
            qa[mi][kc][1] = f2h2(x1.x * QSC, x1.y * QSC);
            qa[mi][kc][2] = f2h2(x2.x * QSC, x2.y * QSC);
            qa[mi][kc][3] = f2h2(x3.x * QSC, x3.y * QSC);
        }
    }

    // per-lane ldmatrix base offsets (bytes), buffer 0
    const uint32_t ks_base = smem_u32(sK)
        + (uint32_t)((((lane >> 4) & 1) * 8 + (lane & 7)) * KROW)
        + (uint32_t)(((lane >> 3) & 1) * 16);
    const uint32_t vs_base = smem_u32(sV)
        + (uint32_t)((((lane >> 3) & 1) * 8 + (lane & 7)) * KROW)
        + (uint32_t)(((lane >> 4) & 1) * 16);

    float o[2][8][4];
    #pragma unroll
    for (int mi = 0; mi < 2; mi++)
        #pragma unroll
        for (int nt = 0; nt < 8; nt++)
            #pragma unroll
            for (int c = 0; c < 4; c++) o[mi][nt][c] = 0.f;
    float lac[2][2] = {{0.f, 0.f}, {0.f, 0.f}};

    const int ktmax = 4 * qi + 3;
    const int rowg    = qi * BQ + w * 32 + g;    // global row: mi=0, c0/c1
    const int rowlast = qi * BQ + w * 32 + 31;

    // staging coords: thread -> 32 contiguous bytes of one key row
    const int skey = tid >> 2;                    // key row 0..63
    const int sec  = (tid & 3) * 32;              // byte offset within 128B row
    const char* Ksrc0 = reinterpret_cast<const char*>(d_Kh)
        + 2 * (base + (size_t)skey * ROWS) + sec;
    const char* Vsrc0 = reinterpret_cast<const char*>(d_Vh)
        + 2 * (base + (size_t)skey * ROWS) + sec;
    const uint32_t kd0 = smem_u32(sK) + (uint32_t)(skey * KROW + sec);
    const uint32_t vd0 = smem_u32(sV) + (uint32_t)(skey * KROW + sec);

    auto stage = [&](int kt2, int buf) {
        size_t goff = (size_t)kt2 * BK * ROWS * 2;
        uint32_t so  = (uint32_t)(buf * TILEB);
        cp16(kd0 + so,      Ksrc0 + goff);
        cp16(kd0 + so + 16, Ksrc0 + goff + 16);
        cp16(vd0 + so,      Vsrc0 + goff);
        cp16(vd0 + so + 16, Vsrc0 + goff + 16);
    };

    // prologue: tile 0 into buffer 0
    stage(0, 0);
    CP_COMMIT();
    CP_WAIT0();
    __syncthreads();

    for (int kt = 0; kt <= ktmax; kt++) {
        const int cur = kt & 1;

        // stage tile kt+1 into the other buffer (async, fire-and-forget)
        if (kt < ktmax) { stage(kt + 1, cur ^ 1); CP_COMMIT(); }

        if (rowlast >= kt * BK) {          // warp not fully masked
            const uint32_t ksb = ks_base + (uint32_t)(cur * TILEB);
            const uint32_t vsb = vs_base + (uint32_t)(cur * TILEB);
            const bool diag = (kt >= 4 * qi);
            const int  rr0  = rowg - kt * BK;

            // per-warp rotated chunk order: decorrelate SMSP stall points
            #pragma unroll
            for (int jj = 0; jj < 4; jj++) {
                const int j = (jj + w) & 3;
                if (diag && kt * BK + j * 16 > rowlast) continue;  // all-masked

                float s[2][2][4];
                #pragma unroll
                for (int mi = 0; mi < 2; mi++)
                    #pragma unroll
                    for (int hh = 0; hh < 2; hh++)
                        #pragma unroll
                        for (int c = 0; c < 4; c++) s[mi][hh][c] = 0.f;

                #pragma unroll
                for (int kc = 0; kc < 4; kc++) {
                    uint32_t kr[4];
                    ldsm_x4(kr, ksb + (uint32_t)(j * 16 * KROW + kc * 32));
                    mma_f16(s[0][0], qa[0][kc], kr[0], kr[1]);
                    mma_f16(s[0][1], qa[0][kc], kr[2], kr[3]);
                    mma_f16(s[1][0], qa[1][kc], kr[0], kr[1]);
                    mma_f16(s[1][1], qa[1][kc], kr[2], kr[3]);
                }

                uint32_t pa[2][4];
                #pragma unroll
                for (int mi = 0; mi < 2; mi++) {
                    float* sl = s[mi][0];
                    float* sh = s[mi][1];
                    if (diag) {
                        int r0 = rr0 + mi * 16, r1 = r0 + 8;
                        int cl = j * 16 + 2 * t4;
                        int ch = cl + 8;
                        if (cl     > r0) sl[0] = -1e30f;
                        if (cl + 1 > r0) sl[1] = -1e30f;
                        if (cl     > r1) sl[2] = -1e30f;
                        if (cl + 1 > r1) sl[3] = -1e30f;
                        if (ch     > r0) sh[0] = -1e30f;
                        if (ch + 1 > r0) sh[1] = -1e30f;
                        if (ch     > r1) sh[2] = -1e30f;
                        if (ch + 1 > r1) sh[3] = -1e30f;
                    }
                    pa[mi][0] = ex2h2(f2h2(sl[0], sl[1]));   // row g,   keys lo
                    pa[mi][1] = ex2h2(f2h2(sl[2], sl[3]));   // row g+8
                    pa[mi][2] = ex2h2(f2h2(sh[0], sh[1]));   // row g,   keys hi
                    pa[mi][3] = ex2h2(f2h2(sh[2], sh[3]));   // row g+8
                    // half2 fold: row-g pair and row-g+8 pair, then to fp32
                    uint32_t h0 = hadd2u(pa[mi][0], pa[mi][2]);
                    uint32_t h1 = hadd2u(pa[mi][1], pa[mi][3]);
                    float2 f0 = h22f2(h0), f1 = h22f2(h1);
                    lac[mi][0] += f0.x + f0.y;
                    lac[mi][1] += f1.x + f1.y;
                }

                #pragma unroll
                for (int nt = 0; nt < 4; nt++) {
                    uint32_t vr[4];
                    ldsm_x4_t(vr, vsb + (uint32_t)(j * 16 * KROW + nt * 32));
                    mma_f16(o[0][2 * nt],     pa[0], vr[0], vr[1]);
                    mma_f16(o[0][2 * nt + 1], pa[0], vr[2], vr[3]);
                    mma_f16(o[1][2 * nt],     pa[1], vr[0], vr[1]);
                    mma_f16(o[1][2 * nt + 1], pa[1], vr[2], vr[3]);
                }
            }
        }

        CP_WAIT0();        // tile kt+1 landed (full tile of compute since issue)
        __syncthreads();   // visibility + compute-done before next overwrite
    }

    // ---- epilogue: rowsum across quad, normalize, store ----
    #pragma unroll
    for (int mi = 0; mi < 2; mi++) {
        float l0 = lac[mi][0], l1 = lac[mi][1];
        l0 += __shfl_xor_sync(0xffffffffu, l0, 1);
        l0 += __shfl_xor_sync(0xffffffffu, l0, 2);
        l1 += __shfl_xor_sync(0xffffffffu, l1, 1);
        l1 += __shfl_xor_sync(0xffffffffu, l1, 2);
        float inv0 = 1.0f / l0, inv1 = 1.0f / l1;

        float* Or0 = O + base
            + (size_t)(qi * BQ + w * 32 + mi * 16 + g) * ROWS;
        float* Or1 = Or0 + (size_t)8 * ROWS;
        #pragma unroll
        for (int nt = 0; nt < 8; nt++) {
            int col = nt * 8 + 2 * t4;
            *reinterpret_cast<float2*>(Or0 + col) =
                make_float2(o[mi][nt][0] * inv0, o[mi][nt][1] * inv0);
            *reinterpret_cast<float2*>(Or1 + col) =
                make_float2(o[mi][nt][2] * inv1, o[mi][nt][3] * inv1);
        }
    }
}

extern "C" void kernel_launch(void* const* d_in, const int* in_sizes, int n_in,
                              void* d_out, int out_size)
{
    const float* Q = (const float*)d_in[0];
    const float* K = (const float*)d_in[1];
    const float* V = (const float*)d_in[2];
    float* O = (float*)d_out;

    const int Btot = in_sizes[0] / (SEQ * HEADS * EDIM);   // 4

    cvt_kernel<<<1024, 256>>>(K, V);

    dim3 grid(SEQ / BQ, Btot * HEADS);   // (8, 64)
    dim3 block(256);
    fa_f16_kernel<<<grid, block>>>(Q, O);
}

// round 16
// speedup vs baseline: 1.0365x; 1.0269x over previous
#include <cuda_runtime.h>
#include <cuda_fp16.h>
#include <stdint.h>
#include <math.h>

// Causal MHA forward: fp16 pre-pass for K/V + cp.async-staged fp16 mma kernel.
// BQ=256 (8 warps x 32 rows), BK=128 (dynamic smem double buffer),
// 1 barrier per 128 keys. B=4, L=2048, H=16, E=64. [B,L,H,E] fp32 in/out.

#define HEADS 16
#define SEQ   2048
#define EDIM  64
#define BQ    256
#define BK    128
#define ROWS  1024           // H*E elements between seq positions
#define KROW  144            // smem bytes per key row (64 half + 8 pad)
#define TILEB (BK * KROW)    // 18432 bytes per tile buffer
#define SMTOT (4 * TILEB)    // 73728: K0,K1,V0,V1
#define QSC   0.18033688011112042f   // 0.125 * log2(e)
#define NELEM (4 * SEQ * HEADS * EDIM)   // 8388608

__device__ __half2 d_Kh[NELEM / 2];   // fp16 K, same [B,L,H,E] layout
__device__ __half2 d_Vh[NELEM / 2];   // fp16 V

__device__ __forceinline__ uint32_t smem_u32(const void* p) {
    uint32_t a;
    asm("{ .reg .u64 t; cvta.to.shared.u64 t, %1; cvt.u32.u64 %0, t; }"
        : "=r"(a) : "l"(p));
    return a;
}
__device__ __forceinline__ uint32_t f2h2(float a, float b) {
    __half2 h = __floats2half2_rn(a, b);
    return *reinterpret_cast<uint32_t*>(&h);
}
__device__ __forceinline__ uint32_t ex2h2(uint32_t x) {
    uint32_t r;
    asm("ex2.approx.f16x2 %0, %1;" : "=r"(r) : "r"(x));
    return r;
}
__device__ __forceinline__ float2 h22f2(uint32_t x) {
    return __half22float2(*reinterpret_cast<__half2*>(&x));
}
__device__ __forceinline__ void cp16(uint32_t dst, const void* src) {
    asm volatile("cp.async.cg.shared.global [%0], [%1], 16;"
                 :: "r"(dst), "l"(src));
}
#define CP_COMMIT() asm volatile("cp.async.commit_group;")
#define CP_WAIT0()  asm volatile("cp.async.wait_group 0;" ::: "memory")

__device__ __forceinline__ void ldsm_x4(uint32_t* r, uint32_t addr) {
    asm volatile("ldmatrix.sync.aligned.m8n8.x4.shared.b16 {%0,%1,%2,%3}, [%4];"
                 : "=r"(r[0]), "=r"(r[1]), "=r"(r[2]), "=r"(r[3]) : "r"(addr));
}
__device__ __forceinline__ void ldsm_x4_t(uint32_t* r, uint32_t addr) {
    asm volatile("ldmatrix.sync.aligned.m8n8.x4.trans.shared.b16 {%0,%1,%2,%3}, [%4];"
                 : "=r"(r[0]), "=r"(r[1]), "=r"(r[2]), "=r"(r[3]) : "r"(addr));
}
__device__ __forceinline__ void mma_f16(float* c, const uint32_t* a,
                                        uint32_t b0, uint32_t b1) {
    asm("mma.sync.aligned.m16n8k16.row.col.f32.f16.f16.f32 "
        "{%0,%1,%2,%3}, {%4,%5,%6,%7}, {%8,%9}, {%0,%1,%2,%3};"
        : "+f"(c[0]), "+f"(c[1]), "+f"(c[2]), "+f"(c[3])
        : "r"(a[0]), "r"(a[1]), "r"(a[2]), "r"(a[3]), "r"(b0), "r"(b1));
}

// ---- pre-pass: fp32 -> fp16 conversion of K and V ----
__global__ __launch_bounds__(256)
void cvt_kernel(const float* __restrict__ K, const float* __restrict__ V) {
    int stride = gridDim.x * blockDim.x;
    for (int i = blockIdx.x * blockDim.x + threadIdx.x;
         i < NELEM / 4; i += stride) {
        float4 k = reinterpret_cast<const float4*>(K)[i];
        float4 v = reinterpret_cast<const float4*>(V)[i];
        uint2 kk, vv;
        kk.x = f2h2(k.x, k.y); kk.y = f2h2(k.z, k.w);
        vv.x = f2h2(v.x, v.y); vv.y = f2h2(v.z, v.w);
        reinterpret_cast<uint2*>(d_Kh)[i] = kk;
        reinterpret_cast<uint2*>(d_Vh)[i] = vv;
    }
}

__global__ __launch_bounds__(256, 2)
void fa_f16_kernel(const float* __restrict__ Q, float* __restrict__ O)
{
    extern __shared__ uint8_t sm[];    // [K0 K1 V0 V1], TILEB each

    const int tid  = threadIdx.x;
    const int w    = tid >> 5;          // 0..7
    const int lane = tid & 31;
    const int g    = lane >> 2;
    const int t4   = lane & 3;
    const int qi   = gridDim.x - 1 - blockIdx.x;     // heavy q-tiles first
    const int bh   = blockIdx.y;
    const int b    = bh / HEADS;
    const int h    = bh % HEADS;
    const size_t base = (((size_t)b * SEQ) * HEADS + h) * EDIM;

    // ---- Q A-fragments: 2 x 16-row m-tiles per warp, fp16, base-2 scaled ----
    uint32_t qa[2][4][4];
    #pragma unroll
    for (int mi = 0; mi < 2; mi++) {
        const float* Qr0 = Q + base
            + (size_t)(qi * BQ + w * 32 + mi * 16 + g) * ROWS;
        const float* Qr1 = Qr0 + (size_t)8 * ROWS;
        #pragma unroll
        for (int kc = 0; kc < 4; kc++) {
            int e0 = kc * 16 + 2 * t4;
            float2 x0 = *reinterpret_cast<const float2*>(Qr0 + e0);
            float2 x1 = *reinterpret_cast<const float2*>(Qr1 + e0);
            float2 x2 = *reinterpret_cast<const float2*>(Qr0 + e0 + 8);
            float2 x3 = *reinterpret_cast<const float2*>(Qr1 + e0 + 8);
            qa[mi][kc][0] = f2h2(x0.x * QSC, x0.y * QSC);
            qa[mi][kc][1] = f2h2(x1.x * QSC, x1.y * QSC);
            qa[mi][kc][2] = f2h2(x2.x * QSC, x2.y * QSC);
            qa[mi][kc][3] = f2h2(x3.x * QSC, x3.y * QSC);
        }
    }

    // per-lane ldmatrix base offsets (bytes) within a tile buffer
    const uint32_t smb = smem_u32(sm);
    const uint32_t ks_base = smb
        + (uint32_t)((((lane >> 4) & 1) * 8 + (lane & 7)) * KROW)
        + (uint32_t)(((lane >> 3) & 1) * 16);
    const uint32_t vs_base = smb + 2u * TILEB
        + (uint32_t)((((lane >> 3) & 1) * 8 + (lane & 7)) * KROW)
        + (uint32_t)(((lane >> 4) & 1) * 16);

    float o[2][8][4];
    #pragma unroll
    for (int mi = 0; mi < 2; mi++)
        #pragma unroll
        for (int nt = 0; nt < 8; nt++)
            #pragma unroll
            for (int c = 0; c < 4; c++) o[mi][nt][c] = 0.f;
    float lac[2][2] = {{0.f, 0.f}, {0.f, 0.f}};

    const int ktmax = 2 * qi + 1;
    const int rowg    = qi * BQ + w * 32 + g;    // global row: mi=0, c0/c1
    const int rowlast = qi * BQ + w * 32 + 31;

    // staging coords: 2 threads per key row, 64 bytes each
    const int skey = tid >> 1;                    // key row 0..127
    const int sec  = (tid & 1) * 64;              // byte offset within 128B row
    const char* Ksrc0 = reinterpret_cast<const char*>(d_Kh)
        + 2 * (base + (size_t)skey * ROWS) + sec;
    const char* Vsrc0 = reinterpret_cast<const char*>(d_Vh)
        + 2 * (base + (size_t)skey * ROWS) + sec;
    const uint32_t kd0 = smb + (uint32_t)(skey * KROW + sec);
    const uint32_t vd0 = smb + 2u * TILEB + (uint32_t)(skey * KROW + sec);

    auto stage = [&](int kt2, int buf) {
        size_t goff = (size_t)kt2 * BK * ROWS * 2;
        uint32_t so  = (uint32_t)(buf * TILEB);
        #pragma unroll
        for (int q4 = 0; q4 < 4; q4++) {
            cp16(kd0 + so + q4 * 16, Ksrc0 + goff + q4 * 16);
            cp16(vd0 + so + q4 * 16, Vsrc0 + goff + q4 * 16);
        }
    };

    // prologue: tile 0 into buffer 0
    stage(0, 0);
    CP_COMMIT();
    CP_WAIT0();
    __syncthreads();

    for (int kt = 0; kt <= ktmax; kt++) {
        const int cur = kt & 1;

        // stage tile kt+1 into the other buffer (async, fire-and-forget)
        if (kt < ktmax) { stage(kt + 1, cur ^ 1); CP_COMMIT(); }

        if (rowlast >= kt * BK) {          // warp not fully masked
            const uint32_t ksb = ks_base + (uint32_t)(cur * TILEB);
            const uint32_t vsb = vs_base + (uint32_t)(cur * TILEB);
            const bool diag = (kt >= 2 * qi);
            const int  rr0  = rowg - kt * BK;

            #pragma unroll
            for (int j = 0; j < 8; j++) {
                if (diag && kt * BK + j * 16 > rowlast) break;  // chunk all-masked

                float s[2][2][4];
                #pragma unroll
                for (int mi = 0; mi < 2; mi++)
                    #pragma unroll
                    for (int hh = 0; hh < 2; hh++)
                        #pragma unroll
                        for (int c = 0; c < 4; c++) s[mi][hh][c] = 0.f;

                #pragma unroll
                for (int kc = 0; kc < 4; kc++) {
                    uint32_t kr[4];
                    ldsm_x4(kr, ksb + (uint32_t)(j * 16 * KROW + kc * 32));
                    mma_f16(s[0][0], qa[0][kc], kr[0], kr[1]);
                    mma_f16(s[0][1], qa[0][kc], kr[2], kr[3]);
                    mma_f16(s[1][0], qa[1][kc], kr[0], kr[1]);
                    mma_f16(s[1][1], qa[1][kc], kr[2], kr[3]);
                }

                uint32_t pa[2][4];
                #pragma unroll
                for (int mi = 0; mi < 2; mi++) {
                    float* sl = s[mi][0];
                    float* sh = s[mi][1];
                    if (diag) {
                        int r0 = rr0 + mi * 16, r1 = r0 + 8;
                        int cl = j * 16 + 2 * t4;
                        int ch = cl + 8;
                        if (cl     > r0) sl[0] = -1e30f;
                        if (cl + 1 > r0) sl[1] = -1e30f;
                        if (cl     > r1) sl[2] = -1e30f;
                        if (cl + 1 > r1) sl[3] = -1e30f;
                        if (ch     > r0) sh[0] = -1e30f;
                        if (ch + 1 > r0) sh[1] = -1e30f;
                        if (ch     > r1) sh[2] = -1e30f;
                        if (ch + 1 > r1) sh[3] = -1e30f;
                    }
                    pa[mi][0] = ex2h2(f2h2(sl[0], sl[1]));   // row g,   keys lo
                    pa[mi][1] = ex2h2(f2h2(sl[2], sl[3]));   // row g+8
                    pa[mi][2] = ex2h2(f2h2(sh[0], sh[1]));   // row g,   keys hi
                    pa[mi][3] = ex2h2(f2h2(sh[2], sh[3]));   // row g+8
                    float2 f0 = h22f2(pa[mi][0]), f1 = h22f2(pa[mi][1]);
                    float2 f2v = h22f2(pa[mi][2]), f3 = h22f2(pa[mi][3]);
                    lac[mi][0] += f0.x + f0.y + f2v.x + f2v.y;
                    lac[mi][1] += f1.x + f1.y + f3.x + f3.y;
                }

                #pragma unroll
                for (int nt = 0; nt < 4; nt++) {
                    uint32_t vr[4];
                    ldsm_x4_t(vr, vsb + (uint32_t)(j * 16 * KROW + nt * 32));
                    mma_f16(o[0][2 * nt],     pa[0], vr[0], vr[1]);
                    mma_f16(o[0][2 * nt + 1], pa[0], vr[2], vr[3]);
                    mma_f16(o[1][2 * nt],     pa[1], vr[0], vr[1]);
                    mma_f16(o[1][2 * nt + 1], pa[1], vr[2], vr[3]);
                }
            }
        }

        CP_WAIT0();        // tile kt+1 landed (full tile of compute since issue)
        __syncthreads();   // visibility + compute-done before next overwrite
    }

    // ---- epilogue: rowsum across quad, normalize, store ----
    #pragma unroll
    for (int mi = 0; mi < 2; mi++) {
        float l0 = lac[mi][0], l1 = lac[mi][1];
        l0 += __shfl_xor_sync(0xffffffffu, l0, 1);
        l0 += __shfl_xor_sync(0xffffffffu, l0, 2);
        l1 += __shfl_xor_sync(0xffffffffu, l1, 1);
        l1 += __shfl_xor_sync(0xffffffffu, l1, 2);
        float inv0 = 1.0f / l0, inv1 = 1.0f / l1;

        float* Or0 = O + base
            + (size_t)(qi * BQ + w * 32 + mi * 16 + g) * ROWS;
        float* Or1 = Or0 + (size_t)8 * ROWS;
        #pragma unroll
        for (int nt = 0; nt < 8; nt++) {
            int col = nt * 8 + 2 * t4;
            *reinterpret_cast<float2*>(Or0 + col) =
                make_float2(o[mi][nt][0] * inv0, o[mi][nt][1] * inv0);
            *reinterpret_cast<float2*>(Or1 + col) =
                make_float2(o[mi][nt][2] * inv1, o[mi][nt][3] * inv1);
        }
    }
}

extern "C" void kernel_launch(void* const* d_in, const int* in_sizes, int n_in,
                              void* d_out, int out_size)
{
    const float* Q = (const float*)d_in[0];
    const float* K = (const float*)d_in[1];
    const float* V = (const float*)d_in[2];
    float* O = (float*)d_out;

    const int Btot = in_sizes[0] / (SEQ * HEADS * EDIM);   // 4

    cvt_kernel<<<1024, 256>>>(K, V);

    cudaFuncSetAttribute(fa_f16_kernel,
                         cudaFuncAttributeMaxDynamicSharedMemorySize, SMTOT);
    dim3 grid(SEQ / BQ, Btot * HEADS);   // (8, 64)
    dim3 block(256);
    fa_f16_kernel<<<grid, block, SMTOT>>>(Q, O);
}